// round 14
// baseline (speedup 1.0000x reference)
#include <cuda_runtime.h>
#include <stdint.h>

#define BATCH 8192
// conv1: in [B,1,28,28] -> out [B,32,14,14] (196 pos), k=5 s=2 p=2
// conv2: in [B,32,14,14] -> out [B,64,8,8]  (64 pos),  k=4 s=2 p=2
// fc:    [B,4096] x [10,4096]^T -> [B,10]

// ---------------- device globals (scratch; no cudaMalloc allowed) ------------
__device__ __align__(128) signed char        g_c1[(size_t)BATCH * 196 * 32]; // [n][pos196][c32] int8 dots
__device__ __align__(128) short              g_c2[(size_t)BATCH * 4096];     // [n][pos64][co64] int16 dots
__device__ __align__(128) short              g_fc[(size_t)BATCH * 10];
__device__ __align__(128) unsigned int       g_w1p[32];                      // [co32]: 25-bit packed 5x5
__device__ __align__(128) unsigned int       g_w2b[1024];                    // [co64][tap16], bit=ci
__device__ __align__(128) short              g_corr[576];                    // [class9][co64] border corr
__device__ __align__(128) unsigned int       g_w3A[640];                     // [o10][p64] ch 0..31 (interleaved)
__device__ __align__(128) unsigned int       g_w3B[640];                     // [o10][p64] ch 32..63
// stats: [0:32) sum1 [32:64) sq1 [64:128) sum2 [128:192) sq2 [192:202) sum3 [202:212) sq3
__device__ __align__(128) unsigned long long g_stats[212];

// ---------------- init: reset stats + binarize/pack weights + corr table -----
__global__ void init_kernel(const float* __restrict__ w1,
                            const float* __restrict__ w2,
                            const float* __restrict__ w3) {
    int t = blockIdx.x * blockDim.x + threadIdx.x;
    if (blockIdx.x == 0 && threadIdx.x < 212) g_stats[threadIdx.x] = 0ull;
    if (t < 32) {                        // w1 [32,1,5,5] -> 25-bit word
        unsigned v = 0;
        #pragma unroll
        for (int r = 0; r < 5; r++)
            #pragma unroll
            for (int kx = 0; kx < 5; kx++)
                v |= (unsigned)(w1[(t * 5 + r) * 5 + kx] > 0.f) << (r * 5 + kx);
        g_w1p[t] = v;
    } else if (t < 32 + 1024) {          // w2 [64,32,4,4]: bit ci
        int i = t - 32;
        int co = i >> 4, tap = i & 15;
        int ky = tap >> 2, kx = tap & 3;
        unsigned v = 0;
        #pragma unroll
        for (int ci = 0; ci < 32; ci++)
            v |= (unsigned)(w2[((co * 32 + ci) * 4 + ky) * 4 + kx] > 0.f) << ci;
        g_w2b[i] = v;
    } else if (t < 32 + 1024 + 1280) {   // w3 [10,4096], interleaved bit order
        int i = t - 1056;                // 0..1279
        int hf = (i >= 640);
        int j2 = hf ? i - 640 : i;
        int o = j2 >> 6, p = j2 & 63;
        int cb = hf ? 32 : 0;
        unsigned v = 0;
        #pragma unroll
        for (int jj = 0; jj < 16; jj++) {
            int cLo = cb + 2 * jj;
            v |= (unsigned)(w3[o * 4096 + cLo * 64 + p]       > 0.f) << jj;
            v |= (unsigned)(w3[o * 4096 + (cLo + 1) * 64 + p] > 0.f) << (16 + jj);
        }
        if (hf) g_w3B[o * 64 + p] = v; else g_w3A[o * 64 + p] = v;
    } else if (t < 32 + 1024 + 1280 + 576) {  // corr[cls][co]: popc(w) over invalid taps
        int i = t - 2336;
        int cls = i >> 6, co = i & 63;
        int cy = cls / 3, cx = cls % 3;
        int s = 0;
        #pragma unroll
        for (int tap = 0; tap < 16; tap++) {
            int ky = tap >> 2, kx = tap & 3;
            bool ivy = (cy == 0 && ky < 2) || (cy == 2 && ky >= 2);
            bool ivx = (cx == 0 && kx < 2) || (cx == 2 && kx >= 2);
            if (ivy || ivx) {
                #pragma unroll
                for (int ci = 0; ci < 32; ci++)
                    s += (int)(w2[((co * 32 + ci) * 4 + ky) * 4 + kx] > 0.f);
            }
        }
        g_corr[i] = (short)s;
    }
}

// ---------------- conv1: 25-bit packed windows, store int8 dots (NO stats) ---
__global__ void __launch_bounds__(224) conv1_kernel(const float* __restrict__ x) {
    __shared__ unsigned xv[28], xm[28];       // value bit / nonzero bit per row
    __shared__ unsigned w1s[32];

    int n = blockIdx.x, t = threadIdx.x;
    int warp = t >> 5, lane = t & 31;

    if (t < 32) w1s[t] = g_w1p[t];

    // coalesced ballot-based input packing: 7 warps x 4 rows
    {
        const float* img = x + (size_t)n * 784;
        #pragma unroll
        for (int rr = 0; rr < 4; rr++) {
            int r = warp * 4 + rr;            // 0..27
            float f = (lane < 28) ? img[r * 28 + lane] : 0.f;
            unsigned v = __ballot_sync(0xFFFFFFFFu, f > 0.f);
            unsigned m = __ballot_sync(0xFFFFFFFFu, f != 0.f);
            if (lane == 0) { xv[r] = v & 0x0FFFFFFFu; xm[r] = m & 0x0FFFFFFFu; }
        }
    }
    __syncthreads();

    if (t >= 196) return;
    // build packed 25-bit window
    int y = t / 14, xo = t % 14;
    int iy0 = 2 * y - 2, ix0 = 2 * xo - 2;
    unsigned SV = 0, SM = 0;
    #pragma unroll
    for (int r = 0; r < 5; r++) {
        int iy = iy0 + r;
        if (iy >= 0 && iy < 28) {
            unsigned xvw = xv[iy], xmw = xm[iy];
            unsigned v, m;
            if (ix0 >= 0) { v = xvw >> ix0;     m = xmw >> ix0; }
            else          { v = xvw << (-ix0);  m = xmw << (-ix0); }
            SV |= (v & 31u) << (5 * r);
            SM |= (m & 31u) << (5 * r);
        }
    }
    int basec = __popc(SM);
    unsigned pack[8] = {0, 0, 0, 0, 0, 0, 0, 0};
    #pragma unroll
    for (int co = 0; co < 32; co++) {
        int mm = __popc((SV ^ w1s[co]) & SM);   // single LOP3 + POPC
        int d = basec - 2 * mm;                  // [-25, 25]
        pack[co >> 2] |= ((unsigned)d & 0xFFu) << ((co & 3) * 8);
    }
    uint4* dst = (uint4*)(g_c1 + ((size_t)n * 196 + t) * 32);
    dst[0] = make_uint4(pack[0], pack[1], pack[2], pack[3]);
    dst[1] = make_uint4(pack[4], pack[5], pack[6], pack[7]);
}

// ---------------- stats1: vectorized per-channel sum/sumsq over g_c1 ---------
#define S1_BLOCKS 2048
__global__ void __launch_bounds__(256) stats1_kernel() {
    // each uint4 = 16 int8 values = channel half [p*16, p*16+16), p = t&1
    __shared__ int s_sm[8][2][16], q_sm[8][2][16];
    int t = threadIdx.x, lane = t & 31, wp = t >> 5;
    int par = t & 1;
    size_t U = (size_t)BATCH * 196 * 2;            // uint4 count (row = 2 uint4)
    size_t stride = (size_t)S1_BLOCKS * 256;       // even -> parity fixed
    int s[16], q[16];
    #pragma unroll
    for (int i = 0; i < 16; i++) { s[i] = 0; q[i] = 0; }
    const uint4* base = (const uint4*)g_c1;
    for (size_t g = (size_t)blockIdx.x * 256 + t; g < U; g += stride) {
        uint4 v = base[g];
        unsigned wv[4] = {v.x, v.y, v.z, v.w};
        #pragma unroll
        for (int w = 0; w < 4; w++) {
            #pragma unroll
            for (int j = 0; j < 4; j++) {
                int b = (int)(signed char)(wv[w] >> (8 * j));
                s[w * 4 + j] += b;
                q[w * 4 + j] += b * b;
            }
        }
    }
    // reduce across lanes of same parity (2,4,8,16)
    #pragma unroll
    for (int i = 0; i < 16; i++) {
        #pragma unroll
        for (int d = 2; d <= 16; d <<= 1) {
            s[i] += __shfl_down_sync(0xFFFFFFFFu, s[i], d);
            q[i] += __shfl_down_sync(0xFFFFFFFFu, q[i], d);
        }
    }
    if (lane < 2) {
        #pragma unroll
        for (int i = 0; i < 16; i++) { s_sm[wp][par][i] = s[i]; q_sm[wp][par][i] = q[i]; }
    }
    __syncthreads();
    if (t < 32) {
        int pr = t >> 4, i = t & 15;               // channel = pr*16 + i = t
        int ss = 0, qq = 0;
        #pragma unroll
        for (int w = 0; w < 8; w++) { ss += s_sm[w][pr][i]; qq += q_sm[w][pr][i]; }
        atomicAdd(&g_stats[t],      (unsigned long long)(long long)ss);
        atomicAdd(&g_stats[32 + t], (unsigned long long)(long long)qq);
    }
}

// ---------------- conv2: 2 samples/block, LDS.128 weights, fused stats2 ------
__global__ void __launch_bounds__(512, 2) conv2_kernel(const float* __restrict__ g1,
                                                       const float* __restrict__ b1) {
    __shared__ unsigned h1s[2][196];
    __shared__ __align__(16) unsigned w2s[1024];
    __shared__ int thr1[32];
    __shared__ unsigned flip1;

    int t = threadIdx.x;
    int sub = t >> 8, tl = t & 255;           // sample-half and local role
    int n = blockIdx.x * 2 + sub;
    int lane = t & 31;

    // issue the per-sample dot loads FIRST so they overlap the smem fills
    uint4 a, bb;
    if (tl < 196) {
        const uint4* src = (const uint4*)(g_c1 + ((size_t)n * 196 + tl) * 32);
        a = src[0]; bb = src[1];
    }

    w2s[t] = g_w2b[t];
    w2s[t + 512] = g_w2b[t + 512];
    if (t < 32) {
        // exact INTEGER binarization threshold from bn1 stats: bit = (d > k)
        long long S = (long long)g_stats[t], Q = (long long)g_stats[32 + t];
        double cnt = 8192.0 * 196.0;
        double m = (double)S / cnt;
        double var = (double)Q / cnt - m * m;
        double s = (double)g1[t] / sqrt(var + 1e-5);
        double b = (double)b1[t];
        int k; bool fl;
        if (s > 0.0)      { double tt = fmin(fmax(m - b / s, -600.0), 600.0); k = (int)floor(tt);    fl = false; }
        else if (s < 0.0) { double tt = fmin(fmax(m - b / s, -600.0), 600.0); k = (int)ceil(tt) - 1; fl = true;  }
        else              { k = (b > 0.0) ? -601 : 601; fl = false; }
        thr1[t] = k;
        unsigned f = __ballot_sync(0xFFFFFFFFu, fl);
        if (t == 0) flip1 = f;
    }
    __syncthreads();

    // binarize h1 with pure integer compares
    if (tl < 196) {
        unsigned words[8] = {a.x, a.y, a.z, a.w, bb.x, bb.y, bb.z, bb.w};
        unsigned w = 0;
        #pragma unroll
        for (int k = 0; k < 8; k++) {
            unsigned wd = words[k];
            #pragma unroll
            for (int j = 0; j < 4; j++) {
                int c = k * 4 + j;
                int v = (int)(signed char)(wd >> (j * 8));
                w |= (unsigned)(v > thr1[c]) << c;
            }
        }
        h1s[sub][tl] = w ^ flip1;
    }
    __syncthreads();

    // thread = pair (y, x=2xp, 2xp+1) x 8 channels; warp owns co [wg*8, wg*8+8)
    int pr = tl & 31, wg = tl >> 5;
    int y = pr >> 2, xp = pr & 3;
    int co0 = wg * 8;

    // load 4x6 input window (rows 2y-2.., cols 4xp-2..)
    unsigned inw[24];
    #pragma unroll
    for (int r = 0; r < 4; r++) {
        int iy = 2 * y - 2 + r;
        #pragma unroll
        for (int j = 0; j < 6; j++) {
            int ix = 4 * xp - 2 + j;
            bool valid = (iy >= 0) & (iy < 14) & (ix >= 0) & (ix < 14);
            inw[r * 6 + j] = valid ? h1s[sub][iy * 14 + ix] : 0u;
        }
    }
    int cy  = (y == 0) ? 0 : ((y == 7) ? 2 : 1);
    int cx0 = (xp == 0) ? 0 : 1;
    int cx1 = (xp == 3) ? 2 : 1;
    int cls0 = cy * 3 + cx0, cls1 = cy * 3 + cx1;
    int nval0 = (cy == 1 ? 4 : 2) * (cx0 == 1 ? 4 : 2);
    int nval1 = (cy == 1 ? 4 : 2) * (cx1 == 1 ? 4 : 2);

    // border corrections: 8 shorts each via one 16B ldg (co0 is 8-aligned)
    int4 cc0 = __ldg((const int4*)(g_corr + cls0 * 64 + co0));
    int4 cc1 = __ldg((const int4*)(g_corr + cls1 * 64 + co0));
    const int* c0w = (const int*)&cc0;
    const int* c1w = (const int*)&cc1;

    const uint4* w2s4 = (const uint4*)w2s;
    unsigned u0[4], u1[4];
    int ssave = 0, qsave = 0;
    #pragma unroll
    for (int jj = 0; jj < 4; jj++) {            // pairs of channels
        int dpair0[2], dpair1[2];
        #pragma unroll
        for (int h = 0; h < 2; h++) {
            int j = 2 * jj + h;
            int co = co0 + j;
            int mm0 = 0, mm1 = 0;
            #pragma unroll
            for (int ky = 0; ky < 4; ky++) {    // one LDS.128 per row of taps
                uint4 w = w2s4[co * 4 + ky];
                mm0 += __popc(inw[ky * 6 + 0] ^ w.x) + __popc(inw[ky * 6 + 1] ^ w.y)
                     + __popc(inw[ky * 6 + 2] ^ w.z) + __popc(inw[ky * 6 + 3] ^ w.w);
                mm1 += __popc(inw[ky * 6 + 2] ^ w.x) + __popc(inw[ky * 6 + 3] ^ w.y)
                     + __popc(inw[ky * 6 + 4] ^ w.z) + __popc(inw[ky * 6 + 5] ^ w.w);
            }
            int cr0 = (int)(short)((c0w[j >> 1] >> ((j & 1) * 16)) & 0xFFFF);
            int cr1 = (int)(short)((c1w[j >> 1] >> ((j & 1) * 16)) & 0xFFFF);
            int d0 = 32 * nval0 - 2 * (mm0 - cr0);
            int d1 = 32 * nval1 - 2 * (mm1 - cr1);
            dpair0[h] = d0; dpair1[h] = d1;
            // fused stats2: warp-wide exact integer sums for channel co
            // (warps never straddle samples: warps 0-7 -> sub 0, 8-15 -> sub 1)
            int s = __reduce_add_sync(0xFFFFFFFFu, d0 + d1);
            int q = __reduce_add_sync(0xFFFFFFFFu, d0 * d0 + d1 * d1);
            if (lane == j) { ssave = s; qsave = q; }
        }
        u0[jj] = ((unsigned)dpair0[0] & 0xFFFFu) | ((unsigned)dpair0[1] << 16);
        u1[jj] = ((unsigned)dpair1[0] & 0xFFFFu) | ((unsigned)dpair1[1] << 16);
    }
    // store both positions: [n][pos][co0..co0+7] int16 = one uint4 each
    int pos0 = y * 8 + 2 * xp;
    uint4* dst0 = (uint4*)(g_c2 + (size_t)n * 4096 + pos0 * 64 + co0);
    uint4* dst1 = (uint4*)(g_c2 + (size_t)n * 4096 + (pos0 + 1) * 64 + co0);
    dst0[0] = make_uint4(u0[0], u0[1], u0[2], u0[3]);
    dst1[0] = make_uint4(u1[0], u1[1], u1[2], u1[3]);

    // warp owns its 8 channels exclusively -> fire-and-forget REDs, lanes 0..7
    if (lane < 8) {
        atomicAdd(&g_stats[64 + co0 + lane],  (unsigned long long)(long long)ssave);
        atomicAdd(&g_stats[128 + co0 + lane], (unsigned long long)(long long)qsave);
    }
}

// ---------------- fc: warp-per-sample, full prefetch, vcmpgts2 binarize ------
__global__ void __launch_bounds__(128, 4) fc_kernel(const float* __restrict__ g2,
                                                    const float* __restrict__ b2) {
    __shared__ unsigned w3sA[640], w3sB[640];
    __shared__ short thk[64];
    __shared__ int flg[64];
    __shared__ unsigned thr2[32];
    __shared__ unsigned flipA, flipB;
    __shared__ int blkS[4][10], blkQ[4][10];

    int t = threadIdx.x, warp = t >> 5, lane = t & 31;
    #pragma unroll
    for (int i = 0; i < 5; i++) { w3sA[t + i * 128] = g_w3A[t + i * 128]; w3sB[t + i * 128] = g_w3B[t + i * 128]; }
    if (t < 64) {
        long long S = (long long)g_stats[64 + t], Q = (long long)g_stats[128 + t];
        double cnt = 8192.0 * 64.0;
        double m = (double)S / cnt;
        double var = (double)Q / cnt - m * m;
        double s = (double)g2[t] / sqrt(var + 1e-5);
        double b = (double)b2[t];
        int k; int fl;
        if (s > 0.0)      { double tt = fmin(fmax(m - b / s, -600.0), 600.0); k = (int)floor(tt);    fl = 0; }
        else if (s < 0.0) { double tt = fmin(fmax(m - b / s, -600.0), 600.0); k = (int)ceil(tt) - 1; fl = 1; }
        else              { k = (b > 0.0) ? -601 : 601; fl = 0; }
        thk[t] = (short)k;
        flg[t] = fl;
    }
    __syncthreads();
    if (t < 32) thr2[t] = ((unsigned)(unsigned short)thk[2 * t]) | ((unsigned)(unsigned short)thk[2 * t + 1] << 16);
    if (t == 32) {
        unsigned fA = 0, fB = 0;
        #pragma unroll
        for (int j = 0; j < 16; j++) {
            fA |= ((unsigned)flg[2 * j] << j)      | ((unsigned)flg[2 * j + 1] << (16 + j));
            fB |= ((unsigned)flg[32 + 2 * j] << j) | ((unsigned)flg[33 + 2 * j] << (16 + j));
        }
        flipA = fA; flipB = fB;
    }
    __syncthreads();

    int samp = blockIdx.x * 4 + warp;

    // prefetch all 128 int16 (two positions) -> 16 outstanding LDG.128
    uint4 v[16];
    const uint4* src0 = (const uint4*)(g_c2 + (size_t)samp * 4096 + lane * 64);
    const uint4* src1 = (const uint4*)(g_c2 + (size_t)samp * 4096 + (lane + 32) * 64);
    #pragma unroll
    for (int k = 0; k < 8; k++) { v[k] = src0[k]; v[8 + k] = src1[k]; }

    int mm[10];
    #pragma unroll
    for (int o = 0; o < 10; o++) mm[o] = 0;

    #pragma unroll
    for (int pp = 0; pp < 2; pp++) {
        int p = lane + pp * 32;
        unsigned accA = 0, accB = 0;
        #pragma unroll
        for (int k = 0; k < 8; k++) {
            unsigned wv[4] = {v[pp * 8 + k].x, v[pp * 8 + k].y, v[pp * 8 + k].z, v[pp * 8 + k].w};
            #pragma unroll
            for (int i = 0; i < 4; i++) {
                int j = 4 * k + i;
                unsigned m = __vcmpgts2(wv[i], thr2[j]);   // SIMD int16 >, mask per half
                if (j < 16) accA |= (m << j)        & (0x00010001u << j);
                else        accB |= (m << (j - 16)) & (0x00010001u << (j - 16));
            }
        }
        accA ^= flipA; accB ^= flipB;
        #pragma unroll
        for (int o = 0; o < 10; o++)
            mm[o] += __popc(accA ^ w3sA[o * 64 + p]) + __popc(accB ^ w3sB[o * 64 + p]);
    }

    int r[10];
    #pragma unroll
    for (int o = 0; o < 10; o++)
        r[o] = 4096 - 2 * __reduce_add_sync(0xFFFFFFFFu, mm[o]);

    if (lane < 10) {
        int vv = 0;
        #pragma unroll
        for (int o = 0; o < 10; o++) if (lane == o) vv = r[o];
        g_fc[(size_t)samp * 10 + lane] = (short)vv;
        blkS[warp][lane] = vv;
        blkQ[warp][lane] = vv * vv;
    }
    __syncthreads();
    if (t < 10) {
        int s = blkS[0][t] + blkS[1][t] + blkS[2][t] + blkS[3][t];
        int q = blkQ[0][t] + blkQ[1][t] + blkQ[2][t] + blkQ[3][t];
        atomicAdd(&g_stats[192 + t], (unsigned long long)(long long)s);
        atomicAdd(&g_stats[202 + t], (unsigned long long)(long long)q);
    }
}

// ---------------- final BN1d epilogue ----------------------------------------
__global__ void __launch_bounds__(256) out_kernel(const float* __restrict__ g3,
                                                  const float* __restrict__ b3,
                                                  float* __restrict__ out) {
    __shared__ float sc[10], sh[10];
    int t = threadIdx.x;
    if (t < 10) {
        long long s = (long long)g_stats[192 + t], q = (long long)g_stats[202 + t];
        double m   = (double)s / 8192.0;
        double var = (double)q / 8192.0 - m * m;
        double scale = (double)g3[t] / sqrt(var + 1e-5);
        sc[t] = (float)scale;
        sh[t] = (float)((double)b3[t] - m * scale);
    }
    __syncthreads();
    int i = blockIdx.x * 256 + t;
    if (i < BATCH * 10) {
        int o = i % 10;
        out[i] = fmaf((float)g_fc[i], sc[o], sh[o]);
    }
}

// ---------------- launch ------------------------------------------------------
extern "C" void kernel_launch(void* const* d_in, const int* in_sizes, int n_in,
                              void* d_out, int out_size) {
    const float* x  = (const float*)d_in[0];
    const float* w1 = (const float*)d_in[1];
    const float* g1 = (const float*)d_in[2];
    const float* b1 = (const float*)d_in[3];
    const float* w2 = (const float*)d_in[4];
    const float* g2 = (const float*)d_in[5];
    const float* b2 = (const float*)d_in[6];
    const float* w3 = (const float*)d_in[7];
    const float* g3 = (const float*)d_in[8];
    const float* b3 = (const float*)d_in[9];
    float* out = (float*)d_out;

    init_kernel<<<12, 256>>>(w1, w2, w3);
    conv1_kernel<<<BATCH, 224>>>(x);
    stats1_kernel<<<S1_BLOCKS, 256>>>();
    conv2_kernel<<<BATCH / 2, 512>>>(g1, b1);   // 4th launch -> ncu capture slot
    fc_kernel<<<BATCH / 4, 128>>>(g2, b2);
    out_kernel<<<(BATCH * 10 + 255) / 256, 256>>>(g3, b3, out);
}

// round 15
// speedup vs baseline: 1.1537x; 1.1537x over previous
#include <cuda_runtime.h>
#include <stdint.h>

#define BATCH 8192
// conv1: in [B,1,28,28] -> out [B,32,14,14] (196 pos), k=5 s=2 p=2
// conv2: in [B,32,14,14] -> out [B,64,8,8]  (64 pos),  k=4 s=2 p=2
// fc:    [B,4096] x [10,4096]^T -> [B,10]

// ---------------- device globals (scratch; no cudaMalloc allowed) ------------
__device__ __align__(128) signed char        g_c1[(size_t)BATCH * 196 * 32]; // [n][pos196][c32] int8 dots
__device__ __align__(128) short              g_c2[(size_t)BATCH * 4096];     // [n][pos64][co64] int16 dots
__device__ __align__(128) short              g_fc[(size_t)BATCH * 10];
__device__ __align__(128) unsigned int       g_w1p[32];                      // [co32]: 25-bit packed 5x5
__device__ __align__(128) unsigned int       g_w2b[1024];                    // [co64][tap16], bit=ci
__device__ __align__(128) short              g_corr[576];                    // [class9][co64] border corr
__device__ __align__(128) unsigned int       g_w3A[640];                     // [o10][p64] ch 0..31 (interleaved)
__device__ __align__(128) unsigned int       g_w3B[640];                     // [o10][p64] ch 32..63
// stats: [0:32) sum1 [32:64) sq1 [64:128) sum2 [128:192) sq2 [192:202) sum3 [202:212) sq3
__device__ __align__(128) unsigned long long g_stats[212];

// ---------------- init: reset stats + binarize/pack weights + corr table -----
__global__ void init_kernel(const float* __restrict__ w1,
                            const float* __restrict__ w2,
                            const float* __restrict__ w3) {
    int t = blockIdx.x * blockDim.x + threadIdx.x;
    if (blockIdx.x == 0 && threadIdx.x < 212) g_stats[threadIdx.x] = 0ull;
    if (t < 32) {                        // w1 [32,1,5,5] -> 25-bit word
        unsigned v = 0;
        #pragma unroll
        for (int r = 0; r < 5; r++)
            #pragma unroll
            for (int kx = 0; kx < 5; kx++)
                v |= (unsigned)(w1[(t * 5 + r) * 5 + kx] > 0.f) << (r * 5 + kx);
        g_w1p[t] = v;
    } else if (t < 32 + 1024) {          // w2 [64,32,4,4]: bit ci
        int i = t - 32;
        int co = i >> 4, tap = i & 15;
        int ky = tap >> 2, kx = tap & 3;
        unsigned v = 0;
        #pragma unroll
        for (int ci = 0; ci < 32; ci++)
            v |= (unsigned)(w2[((co * 32 + ci) * 4 + ky) * 4 + kx] > 0.f) << ci;
        g_w2b[i] = v;
    } else if (t < 32 + 1024 + 1280) {   // w3 [10,4096], interleaved bit order
        int i = t - 1056;                // 0..1279
        int hf = (i >= 640);
        int j2 = hf ? i - 640 : i;
        int o = j2 >> 6, p = j2 & 63;
        int cb = hf ? 32 : 0;
        unsigned v = 0;
        #pragma unroll
        for (int jj = 0; jj < 16; jj++) {
            int cLo = cb + 2 * jj;
            v |= (unsigned)(w3[o * 4096 + cLo * 64 + p]       > 0.f) << jj;
            v |= (unsigned)(w3[o * 4096 + (cLo + 1) * 64 + p] > 0.f) << (16 + jj);
        }
        if (hf) g_w3B[o * 64 + p] = v; else g_w3A[o * 64 + p] = v;
    } else if (t < 32 + 1024 + 1280 + 576) {  // corr[cls][co]: popc(w) over invalid taps
        int i = t - 2336;
        int cls = i >> 6, co = i & 63;
        int cy = cls / 3, cx = cls % 3;
        int s = 0;
        #pragma unroll
        for (int tap = 0; tap < 16; tap++) {
            int ky = tap >> 2, kx = tap & 3;
            bool ivy = (cy == 0 && ky < 2) || (cy == 2 && ky >= 2);
            bool ivx = (cx == 0 && kx < 2) || (cx == 2 && kx >= 2);
            if (ivy || ivx) {
                #pragma unroll
                for (int ci = 0; ci < 32; ci++)
                    s += (int)(w2[((co * 32 + ci) * 4 + ky) * 4 + kx] > 0.f);
            }
        }
        g_corr[i] = (short)s;
    }
}

// ---------------- conv1: 25-bit packed windows, store int8 dots (NO stats) ---
__global__ void __launch_bounds__(224) conv1_kernel(const float* __restrict__ x) {
    __shared__ unsigned xv[28], xm[28];       // value bit / nonzero bit per row
    __shared__ unsigned w1s[32];

    int n = blockIdx.x, t = threadIdx.x;
    int warp = t >> 5, lane = t & 31;

    if (t < 32) w1s[t] = g_w1p[t];

    // coalesced ballot-based input packing: 7 warps x 4 rows
    {
        const float* img = x + (size_t)n * 784;
        #pragma unroll
        for (int rr = 0; rr < 4; rr++) {
            int r = warp * 4 + rr;            // 0..27
            float f = (lane < 28) ? img[r * 28 + lane] : 0.f;
            unsigned v = __ballot_sync(0xFFFFFFFFu, f > 0.f);
            unsigned m = __ballot_sync(0xFFFFFFFFu, f != 0.f);
            if (lane == 0) { xv[r] = v & 0x0FFFFFFFu; xm[r] = m & 0x0FFFFFFFu; }
        }
    }
    __syncthreads();

    if (t >= 196) return;
    // build packed 25-bit window
    int y = t / 14, xo = t % 14;
    int iy0 = 2 * y - 2, ix0 = 2 * xo - 2;
    unsigned SV = 0, SM = 0;
    #pragma unroll
    for (int r = 0; r < 5; r++) {
        int iy = iy0 + r;
        if (iy >= 0 && iy < 28) {
            unsigned xvw = xv[iy], xmw = xm[iy];
            unsigned v, m;
            if (ix0 >= 0) { v = xvw >> ix0;     m = xmw >> ix0; }
            else          { v = xvw << (-ix0);  m = xmw << (-ix0); }
            SV |= (v & 31u) << (5 * r);
            SM |= (m & 31u) << (5 * r);
        }
    }
    int basec = __popc(SM);
    unsigned pack[8] = {0, 0, 0, 0, 0, 0, 0, 0};
    #pragma unroll
    for (int co = 0; co < 32; co++) {
        int mm = __popc((SV ^ w1s[co]) & SM);   // single LOP3 + POPC
        int d = basec - 2 * mm;                  // [-25, 25]
        pack[co >> 2] |= ((unsigned)d & 0xFFu) << ((co & 3) * 8);
    }
    uint4* dst = (uint4*)(g_c1 + ((size_t)n * 196 + t) * 32);
    dst[0] = make_uint4(pack[0], pack[1], pack[2], pack[3]);
    dst[1] = make_uint4(pack[4], pack[5], pack[6], pack[7]);
}

// ---------------- stats1: vectorized per-channel sum/sumsq over g_c1 ---------
#define S1_BLOCKS 2048
__global__ void __launch_bounds__(256) stats1_kernel() {
    // each uint4 = 16 int8 values = channel half [p*16, p*16+16), p = t&1
    __shared__ int s_sm[8][2][16], q_sm[8][2][16];
    int t = threadIdx.x, lane = t & 31, wp = t >> 5;
    int par = t & 1;
    size_t U = (size_t)BATCH * 196 * 2;            // uint4 count (row = 2 uint4)
    size_t stride = (size_t)S1_BLOCKS * 256;       // even -> parity fixed
    int s[16], q[16];
    #pragma unroll
    for (int i = 0; i < 16; i++) { s[i] = 0; q[i] = 0; }
    const uint4* base = (const uint4*)g_c1;
    for (size_t g = (size_t)blockIdx.x * 256 + t; g < U; g += stride) {
        uint4 v = base[g];
        unsigned wv[4] = {v.x, v.y, v.z, v.w};
        #pragma unroll
        for (int w = 0; w < 4; w++) {
            #pragma unroll
            for (int j = 0; j < 4; j++) {
                int b = (int)(signed char)(wv[w] >> (8 * j));
                s[w * 4 + j] += b;
                q[w * 4 + j] += b * b;
            }
        }
    }
    // reduce across lanes of same parity (2,4,8,16)
    #pragma unroll
    for (int i = 0; i < 16; i++) {
        #pragma unroll
        for (int d = 2; d <= 16; d <<= 1) {
            s[i] += __shfl_down_sync(0xFFFFFFFFu, s[i], d);
            q[i] += __shfl_down_sync(0xFFFFFFFFu, q[i], d);
        }
    }
    if (lane < 2) {
        #pragma unroll
        for (int i = 0; i < 16; i++) { s_sm[wp][par][i] = s[i]; q_sm[wp][par][i] = q[i]; }
    }
    __syncthreads();
    if (t < 32) {
        int pr = t >> 4, i = t & 15;               // channel = pr*16 + i = t
        int ss = 0, qq = 0;
        #pragma unroll
        for (int w = 0; w < 8; w++) { ss += s_sm[w][pr][i]; qq += q_sm[w][pr][i]; }
        atomicAdd(&g_stats[t],      (unsigned long long)(long long)ss);
        atomicAdd(&g_stats[32 + t], (unsigned long long)(long long)qq);
    }
}

// ---------------- conv2: LDS.128 weights + fused stats2 (REDUX) --------------
__global__ void __launch_bounds__(256, 4) conv2_kernel(const float* __restrict__ g1,
                                                       const float* __restrict__ b1) {
    __shared__ unsigned h1s[196];
    __shared__ __align__(16) unsigned w2s[1024];
    __shared__ int thr1[32];
    __shared__ unsigned flip1;

    int n = blockIdx.x, t = threadIdx.x;
    int lane = t & 31;

    // issue the per-sample dot loads FIRST so they overlap the smem fills
    uint4 a, bb;
    if (t < 196) {
        const uint4* src = (const uint4*)(g_c1 + ((size_t)n * 196 + t) * 32);
        a = src[0]; bb = src[1];
    }

    #pragma unroll
    for (int i = 0; i < 4; i++) w2s[t + i * 256] = g_w2b[t + i * 256];
    if (t < 32) {
        // exact INTEGER binarization threshold from bn1 stats: bit = (d > k)
        long long S = (long long)g_stats[t], Q = (long long)g_stats[32 + t];
        double cnt = 8192.0 * 196.0;
        double m = (double)S / cnt;
        double var = (double)Q / cnt - m * m;
        double s = (double)g1[t] / sqrt(var + 1e-5);
        double b = (double)b1[t];
        int k; bool fl;
        if (s > 0.0)      { double tt = fmin(fmax(m - b / s, -600.0), 600.0); k = (int)floor(tt);    fl = false; }
        else if (s < 0.0) { double tt = fmin(fmax(m - b / s, -600.0), 600.0); k = (int)ceil(tt) - 1; fl = true;  }
        else              { k = (b > 0.0) ? -601 : 601; fl = false; }
        thr1[t] = k;
        unsigned f = __ballot_sync(0xFFFFFFFFu, fl);
        if (t == 0) flip1 = f;
    }
    __syncthreads();

    // binarize h1 with pure integer compares
    if (t < 196) {
        unsigned words[8] = {a.x, a.y, a.z, a.w, bb.x, bb.y, bb.z, bb.w};
        unsigned w = 0;
        #pragma unroll
        for (int k = 0; k < 8; k++) {
            unsigned wd = words[k];
            #pragma unroll
            for (int j = 0; j < 4; j++) {
                int c = k * 4 + j;
                int v = (int)(signed char)(wd >> (j * 8));
                w |= (unsigned)(v > thr1[c]) << c;
            }
        }
        h1s[t] = w ^ flip1;
    }
    __syncthreads();

    // thread = pair (y, x=2xp, 2xp+1) x 8 channels; warp owns co [wg*8, wg*8+8)
    int pr = t & 31, wg = t >> 5;
    int y = pr >> 2, xp = pr & 3;
    int co0 = wg * 8;

    // load 4x6 input window (rows 2y-2.., cols 4xp-2..)
    unsigned inw[24];
    #pragma unroll
    for (int r = 0; r < 4; r++) {
        int iy = 2 * y - 2 + r;
        #pragma unroll
        for (int j = 0; j < 6; j++) {
            int ix = 4 * xp - 2 + j;
            bool valid = (iy >= 0) & (iy < 14) & (ix >= 0) & (ix < 14);
            inw[r * 6 + j] = valid ? h1s[iy * 14 + ix] : 0u;
        }
    }
    int cy  = (y == 0) ? 0 : ((y == 7) ? 2 : 1);
    int cx0 = (xp == 0) ? 0 : 1;
    int cx1 = (xp == 3) ? 2 : 1;
    int cls0 = cy * 3 + cx0, cls1 = cy * 3 + cx1;
    int nval0 = (cy == 1 ? 4 : 2) * (cx0 == 1 ? 4 : 2);
    int nval1 = (cy == 1 ? 4 : 2) * (cx1 == 1 ? 4 : 2);

    // border corrections: 8 shorts each via one 16B ldg (co0 is 8-aligned)
    int4 cc0 = __ldg((const int4*)(g_corr + cls0 * 64 + co0));
    int4 cc1 = __ldg((const int4*)(g_corr + cls1 * 64 + co0));
    const int* c0w = (const int*)&cc0;
    const int* c1w = (const int*)&cc1;

    const uint4* w2s4 = (const uint4*)w2s;
    unsigned u0[4], u1[4];
    int ssave = 0, qsave = 0;
    #pragma unroll
    for (int jj = 0; jj < 4; jj++) {            // pairs of channels
        int dpair0[2], dpair1[2];
        #pragma unroll
        for (int h = 0; h < 2; h++) {
            int j = 2 * jj + h;
            int co = co0 + j;
            int mm0 = 0, mm1 = 0;
            #pragma unroll
            for (int ky = 0; ky < 4; ky++) {    // one LDS.128 per row of taps
                uint4 w = w2s4[co * 4 + ky];
                mm0 += __popc(inw[ky * 6 + 0] ^ w.x) + __popc(inw[ky * 6 + 1] ^ w.y)
                     + __popc(inw[ky * 6 + 2] ^ w.z) + __popc(inw[ky * 6 + 3] ^ w.w);
                mm1 += __popc(inw[ky * 6 + 2] ^ w.x) + __popc(inw[ky * 6 + 3] ^ w.y)
                     + __popc(inw[ky * 6 + 4] ^ w.z) + __popc(inw[ky * 6 + 5] ^ w.w);
            }
            int cr0 = (int)(short)((c0w[j >> 1] >> ((j & 1) * 16)) & 0xFFFF);
            int cr1 = (int)(short)((c1w[j >> 1] >> ((j & 1) * 16)) & 0xFFFF);
            int d0 = 32 * nval0 - 2 * (mm0 - cr0);
            int d1 = 32 * nval1 - 2 * (mm1 - cr1);
            dpair0[h] = d0; dpair1[h] = d1;
            // fused stats2: warp-wide exact integer sums for channel co
            int s = __reduce_add_sync(0xFFFFFFFFu, d0 + d1);
            int q = __reduce_add_sync(0xFFFFFFFFu, d0 * d0 + d1 * d1);
            if (lane == j) { ssave = s; qsave = q; }
        }
        u0[jj] = ((unsigned)dpair0[0] & 0xFFFFu) | ((unsigned)dpair0[1] << 16);
        u1[jj] = ((unsigned)dpair1[0] & 0xFFFFu) | ((unsigned)dpair1[1] << 16);
    }
    // store both positions: [n][pos][co0..co0+7] int16 = one uint4 each
    int pos0 = y * 8 + 2 * xp;
    uint4* dst0 = (uint4*)(g_c2 + (size_t)n * 4096 + pos0 * 64 + co0);
    uint4* dst1 = (uint4*)(g_c2 + (size_t)n * 4096 + (pos0 + 1) * 64 + co0);
    dst0[0] = make_uint4(u0[0], u0[1], u0[2], u0[3]);
    dst1[0] = make_uint4(u1[0], u1[1], u1[2], u1[3]);

    // warp owns its 8 channels exclusively -> fire-and-forget REDs, lanes 0..7
    if (lane < 8) {
        atomicAdd(&g_stats[64 + co0 + lane],  (unsigned long long)(long long)ssave);
        atomicAdd(&g_stats[128 + co0 + lane], (unsigned long long)(long long)qsave);
    }
}

// ---------------- fc: 8 samples/block, full prefetch, vcmpgts2 binarize ------
__global__ void __launch_bounds__(256, 2) fc_kernel(const float* __restrict__ g2,
                                                    const float* __restrict__ b2) {
    __shared__ unsigned w3sA[640], w3sB[640];
    __shared__ short thk[64];
    __shared__ int flg[64];
    __shared__ unsigned thr2[32];
    __shared__ unsigned flipA, flipB;
    __shared__ int blkS[8][10], blkQ[8][10];

    int t = threadIdx.x, warp = t >> 5, lane = t & 31;
    #pragma unroll
    for (int i = 0; i < 3; i++) {
        int idx = t + i * 256;
        if (idx < 640) { w3sA[idx] = g_w3A[idx]; w3sB[idx] = g_w3B[idx]; }
    }
    if (t < 64) {
        long long S = (long long)g_stats[64 + t], Q = (long long)g_stats[128 + t];
        double cnt = 8192.0 * 64.0;
        double m = (double)S / cnt;
        double var = (double)Q / cnt - m * m;
        double s = (double)g2[t] / sqrt(var + 1e-5);
        double b = (double)b2[t];
        int k; int fl;
        if (s > 0.0)      { double tt = fmin(fmax(m - b / s, -600.0), 600.0); k = (int)floor(tt);    fl = 0; }
        else if (s < 0.0) { double tt = fmin(fmax(m - b / s, -600.0), 600.0); k = (int)ceil(tt) - 1; fl = 1; }
        else              { k = (b > 0.0) ? -601 : 601; fl = 0; }
        thk[t] = (short)k;
        flg[t] = fl;
    }
    __syncthreads();
    if (t < 32) thr2[t] = ((unsigned)(unsigned short)thk[2 * t]) | ((unsigned)(unsigned short)thk[2 * t + 1] << 16);
    if (t == 32) {
        unsigned fA = 0, fB = 0;
        #pragma unroll
        for (int j = 0; j < 16; j++) {
            fA |= ((unsigned)flg[2 * j] << j)      | ((unsigned)flg[2 * j + 1] << (16 + j));
            fB |= ((unsigned)flg[32 + 2 * j] << j) | ((unsigned)flg[33 + 2 * j] << (16 + j));
        }
        flipA = fA; flipB = fB;
    }
    __syncthreads();

    int samp = blockIdx.x * 8 + warp;

    // prefetch all 128 int16 (two positions) -> 16 outstanding LDG.128
    uint4 v[16];
    const uint4* src0 = (const uint4*)(g_c2 + (size_t)samp * 4096 + lane * 64);
    const uint4* src1 = (const uint4*)(g_c2 + (size_t)samp * 4096 + (lane + 32) * 64);
    #pragma unroll
    for (int k = 0; k < 8; k++) { v[k] = src0[k]; v[8 + k] = src1[k]; }

    int mm[10];
    #pragma unroll
    for (int o = 0; o < 10; o++) mm[o] = 0;

    #pragma unroll
    for (int pp = 0; pp < 2; pp++) {
        int p = lane + pp * 32;
        unsigned accA = 0, accB = 0;
        #pragma unroll
        for (int k = 0; k < 8; k++) {
            unsigned wv[4] = {v[pp * 8 + k].x, v[pp * 8 + k].y, v[pp * 8 + k].z, v[pp * 8 + k].w};
            #pragma unroll
            for (int i = 0; i < 4; i++) {
                int j = 4 * k + i;
                unsigned m = __vcmpgts2(wv[i], thr2[j]);   // SIMD int16 >, mask per half
                if (j < 16) accA |= (m << j)        & (0x00010001u << j);
                else        accB |= (m << (j - 16)) & (0x00010001u << (j - 16));
            }
        }
        accA ^= flipA; accB ^= flipB;
        #pragma unroll
        for (int o = 0; o < 10; o++)
            mm[o] += __popc(accA ^ w3sA[o * 64 + p]) + __popc(accB ^ w3sB[o * 64 + p]);
    }

    int r[10];
    #pragma unroll
    for (int o = 0; o < 10; o++)
        r[o] = 4096 - 2 * __reduce_add_sync(0xFFFFFFFFu, mm[o]);

    if (lane < 10) {
        int vv = 0;
        #pragma unroll
        for (int o = 0; o < 10; o++) if (lane == o) vv = r[o];
        g_fc[(size_t)samp * 10 + lane] = (short)vv;
        blkS[warp][lane] = vv;
        blkQ[warp][lane] = vv * vv;
    }
    __syncthreads();
    if (t < 10) {
        int s = 0, q = 0;
        #pragma unroll
        for (int w = 0; w < 8; w++) { s += blkS[w][t]; q += blkQ[w][t]; }
        atomicAdd(&g_stats[192 + t], (unsigned long long)(long long)s);
        atomicAdd(&g_stats[202 + t], (unsigned long long)(long long)q);
    }
}

// ---------------- final BN1d epilogue ----------------------------------------
__global__ void __launch_bounds__(256) out_kernel(const float* __restrict__ g3,
                                                  const float* __restrict__ b3,
                                                  float* __restrict__ out) {
    __shared__ float sc[10], sh[10];
    int t = threadIdx.x;
    if (t < 10) {
        long long s = (long long)g_stats[192 + t], q = (long long)g_stats[202 + t];
        double m   = (double)s / 8192.0;
        double var = (double)q / 8192.0 - m * m;
        double scale = (double)g3[t] / sqrt(var + 1e-5);
        sc[t] = (float)scale;
        sh[t] = (float)((double)b3[t] - m * scale);
    }
    __syncthreads();
    int i = blockIdx.x * 256 + t;
    if (i < BATCH * 10) {
        int o = i % 10;
        out[i] = fmaf((float)g_fc[i], sc[o], sh[o]);
    }
}

// ---------------- launch ------------------------------------------------------
extern "C" void kernel_launch(void* const* d_in, const int* in_sizes, int n_in,
                              void* d_out, int out_size) {
    const float* x  = (const float*)d_in[0];
    const float* w1 = (const float*)d_in[1];
    const float* g1 = (const float*)d_in[2];
    const float* b1 = (const float*)d_in[3];
    const float* w2 = (const float*)d_in[4];
    const float* g2 = (const float*)d_in[5];
    const float* b2 = (const float*)d_in[6];
    const float* w3 = (const float*)d_in[7];
    const float* g3 = (const float*)d_in[8];
    const float* b3 = (const float*)d_in[9];
    float* out = (float*)d_out;

    init_kernel<<<12, 256>>>(w1, w2, w3);
    conv1_kernel<<<BATCH, 224>>>(x);
    stats1_kernel<<<S1_BLOCKS, 256>>>();
    conv2_kernel<<<BATCH, 256>>>(g1, b1);   // 4th launch -> ncu capture slot
    fc_kernel<<<BATCH / 8, 256>>>(g2, b2);
    out_kernel<<<(BATCH * 10 + 255) / 256, 256>>>(g3, b3, out);
}

// round 16
// speedup vs baseline: 1.1828x; 1.0253x over previous
#include <cuda_runtime.h>
#include <stdint.h>

#define BATCH 8192
// conv1: in [B,1,28,28] -> out [B,32,14,14] (196 pos), k=5 s=2 p=2
// conv2: in [B,32,14,14] -> out [B,64,8,8]  (64 pos),  k=4 s=2 p=2
// fc:    [B,4096] x [10,4096]^T -> [B,10]

// ---------------- device globals (scratch; no cudaMalloc allowed) ------------
__device__ __align__(128) signed char        g_c1[(size_t)BATCH * 196 * 32]; // [n][pos196][c32] int8 dots
__device__ __align__(128) short              g_c2[(size_t)BATCH * 4096];     // [n][pos64][co64] int16 dots
__device__ __align__(128) short              g_fc[(size_t)BATCH * 10];
__device__ __align__(128) unsigned int       g_w1p[32];                      // [co32]: 25-bit packed 5x5
__device__ __align__(128) unsigned int       g_w2b[1024];                    // [co64][tap16], bit=ci
__device__ __align__(128) short              g_corr[576];                    // [class9][co64] border corr
__device__ __align__(128) unsigned int       g_w3A[640];                     // [o10][p64] ch 0..31 (interleaved)
__device__ __align__(128) unsigned int       g_w3B[640];                     // [o10][p64] ch 32..63
// stats: [0:32) sum1 [32:64) sq1 [64:128) sum2 [128:192) sq2 [192:202) sum3 [202:212) sq3
__device__ __align__(128) unsigned long long g_stats[212];

// swizzled row base for conv2's h1s: banks for fixed tap are a bijection
__device__ __forceinline__ int h1base(int iy) {
    return (iy << 5) + ((iy >> 1) & 3) + (((iy >> 3) & 1) << 4);
}

// ---------------- init: reset stats + binarize/pack weights + corr table -----
__global__ void init_kernel(const float* __restrict__ w1,
                            const float* __restrict__ w2,
                            const float* __restrict__ w3) {
    int t = blockIdx.x * blockDim.x + threadIdx.x;
    if (blockIdx.x == 0 && threadIdx.x < 212) g_stats[threadIdx.x] = 0ull;
    if (t < 32) {                        // w1 [32,1,5,5] -> 25-bit word
        unsigned v = 0;
        #pragma unroll
        for (int r = 0; r < 5; r++)
            #pragma unroll
            for (int kx = 0; kx < 5; kx++)
                v |= (unsigned)(w1[(t * 5 + r) * 5 + kx] > 0.f) << (r * 5 + kx);
        g_w1p[t] = v;
    } else if (t < 32 + 1024) {          // w2 [64,32,4,4]: bit ci
        int i = t - 32;
        int co = i >> 4, tap = i & 15;
        int ky = tap >> 2, kx = tap & 3;
        unsigned v = 0;
        #pragma unroll
        for (int ci = 0; ci < 32; ci++)
            v |= (unsigned)(w2[((co * 32 + ci) * 4 + ky) * 4 + kx] > 0.f) << ci;
        g_w2b[i] = v;
    } else if (t < 32 + 1024 + 1280) {   // w3 [10,4096], interleaved bit order
        int i = t - 1056;                // 0..1279
        int hf = (i >= 640);
        int j2 = hf ? i - 640 : i;
        int o = j2 >> 6, p = j2 & 63;
        int cb = hf ? 32 : 0;
        unsigned v = 0;
        #pragma unroll
        for (int jj = 0; jj < 16; jj++) {
            int cLo = cb + 2 * jj;
            v |= (unsigned)(w3[o * 4096 + cLo * 64 + p]       > 0.f) << jj;
            v |= (unsigned)(w3[o * 4096 + (cLo + 1) * 64 + p] > 0.f) << (16 + jj);
        }
        if (hf) g_w3B[o * 64 + p] = v; else g_w3A[o * 64 + p] = v;
    } else if (t < 32 + 1024 + 1280 + 576) {  // corr[cls][co]: popc(w) over invalid taps
        int i = t - 2336;
        int cls = i >> 6, co = i & 63;
        int cy = cls / 3, cx = cls % 3;
        int s = 0;
        #pragma unroll
        for (int tap = 0; tap < 16; tap++) {
            int ky = tap >> 2, kx = tap & 3;
            bool ivy = (cy == 0 && ky < 2) || (cy == 2 && ky >= 2);
            bool ivx = (cx == 0 && kx < 2) || (cx == 2 && kx >= 2);
            if (ivy || ivx) {
                #pragma unroll
                for (int ci = 0; ci < 32; ci++)
                    s += (int)(w2[((co * 32 + ci) * 4 + ky) * 4 + kx] > 0.f);
            }
        }
        g_corr[i] = (short)s;
    }
}

// ---------------- conv1: 25-bit packed windows, store int8 dots (NO stats) ---
__global__ void __launch_bounds__(224) conv1_kernel(const float* __restrict__ x) {
    __shared__ unsigned xv[28], xm[28];       // value bit / nonzero bit per row
    __shared__ unsigned w1s[32];

    int n = blockIdx.x, t = threadIdx.x;
    int warp = t >> 5, lane = t & 31;

    if (t < 32) w1s[t] = g_w1p[t];

    // coalesced ballot-based input packing: 7 warps x 4 rows
    {
        const float* img = x + (size_t)n * 784;
        #pragma unroll
        for (int rr = 0; rr < 4; rr++) {
            int r = warp * 4 + rr;            // 0..27
            float f = (lane < 28) ? img[r * 28 + lane] : 0.f;
            unsigned v = __ballot_sync(0xFFFFFFFFu, f > 0.f);
            unsigned m = __ballot_sync(0xFFFFFFFFu, f != 0.f);
            if (lane == 0) { xv[r] = v & 0x0FFFFFFFu; xm[r] = m & 0x0FFFFFFFu; }
        }
    }
    __syncthreads();

    if (t >= 196) return;
    // build packed 25-bit window
    int y = t / 14, xo = t % 14;
    int iy0 = 2 * y - 2, ix0 = 2 * xo - 2;
    unsigned SV = 0, SM = 0;
    #pragma unroll
    for (int r = 0; r < 5; r++) {
        int iy = iy0 + r;
        if (iy >= 0 && iy < 28) {
            unsigned xvw = xv[iy], xmw = xm[iy];
            unsigned v, m;
            if (ix0 >= 0) { v = xvw >> ix0;     m = xmw >> ix0; }
            else          { v = xvw << (-ix0);  m = xmw << (-ix0); }
            SV |= (v & 31u) << (5 * r);
            SM |= (m & 31u) << (5 * r);
        }
    }
    int basec = __popc(SM);
    unsigned pack[8] = {0, 0, 0, 0, 0, 0, 0, 0};
    #pragma unroll
    for (int co = 0; co < 32; co++) {
        int mm = __popc((SV ^ w1s[co]) & SM);   // single LOP3 + POPC
        int d = basec - 2 * mm;                  // [-25, 25]
        pack[co >> 2] |= ((unsigned)d & 0xFFu) << ((co & 3) * 8);
    }
    uint4* dst = (uint4*)(g_c1 + ((size_t)n * 196 + t) * 32);
    dst[0] = make_uint4(pack[0], pack[1], pack[2], pack[3]);
    dst[1] = make_uint4(pack[4], pack[5], pack[6], pack[7]);
}

// ---------------- stats1: vectorized per-channel sum/sumsq over g_c1 ---------
#define S1_BLOCKS 2048
__global__ void __launch_bounds__(256) stats1_kernel() {
    // each uint4 = 16 int8 values = channel half [p*16, p*16+16), p = t&1
    __shared__ int s_sm[8][2][16], q_sm[8][2][16];
    int t = threadIdx.x, lane = t & 31, wp = t >> 5;
    int par = t & 1;
    size_t U = (size_t)BATCH * 196 * 2;            // uint4 count (row = 2 uint4)
    size_t stride = (size_t)S1_BLOCKS * 256;       // even -> parity fixed
    int s[16], q[16];
    #pragma unroll
    for (int i = 0; i < 16; i++) { s[i] = 0; q[i] = 0; }
    const uint4* base = (const uint4*)g_c1;
    for (size_t g = (size_t)blockIdx.x * 256 + t; g < U; g += stride) {
        uint4 v = base[g];
        unsigned wv[4] = {v.x, v.y, v.z, v.w};
        #pragma unroll
        for (int w = 0; w < 4; w++) {
            #pragma unroll
            for (int j = 0; j < 4; j++) {
                int b = (int)(signed char)(wv[w] >> (8 * j));
                s[w * 4 + j] += b;
                q[w * 4 + j] += b * b;
            }
        }
    }
    // reduce across lanes of same parity (2,4,8,16)
    #pragma unroll
    for (int i = 0; i < 16; i++) {
        #pragma unroll
        for (int d = 2; d <= 16; d <<= 1) {
            s[i] += __shfl_down_sync(0xFFFFFFFFu, s[i], d);
            q[i] += __shfl_down_sync(0xFFFFFFFFu, q[i], d);
        }
    }
    if (lane < 2) {
        #pragma unroll
        for (int i = 0; i < 16; i++) { s_sm[wp][par][i] = s[i]; q_sm[wp][par][i] = q[i]; }
    }
    __syncthreads();
    if (t < 32) {
        int pr = t >> 4, i = t & 15;               // channel = pr*16 + i = t
        int ss = 0, qq = 0;
        #pragma unroll
        for (int w = 0; w < 8; w++) { ss += s_sm[w][pr][i]; qq += q_sm[w][pr][i]; }
        atomicAdd(&g_stats[t],      (unsigned long long)(long long)ss);
        atomicAdd(&g_stats[32 + t], (unsigned long long)(long long)qq);
    }
}

// ---------------- conv2: swizzled h1s (conflict-free), fused stats2 ----------
__global__ void __launch_bounds__(256, 4) conv2_kernel(const float* __restrict__ g1,
                                                       const float* __restrict__ b1) {
    __shared__ unsigned h1s[14 * 32 + 32];    // swizzled: row iy at h1base(iy)
    __shared__ __align__(16) unsigned w2s[1024];
    __shared__ int thr1[32];
    __shared__ unsigned flip1;

    int n = blockIdx.x, t = threadIdx.x;
    int lane = t & 31;

    // issue the per-sample dot loads FIRST so they overlap the smem fills
    uint4 a, bb;
    if (t < 196) {
        const uint4* src = (const uint4*)(g_c1 + ((size_t)n * 196 + t) * 32);
        a = src[0]; bb = src[1];
    }

    #pragma unroll
    for (int i = 0; i < 4; i++) w2s[t + i * 256] = g_w2b[t + i * 256];
    if (t < 32) {
        // exact INTEGER binarization threshold from bn1 stats: bit = (d > k)
        long long S = (long long)g_stats[t], Q = (long long)g_stats[32 + t];
        double cnt = 8192.0 * 196.0;
        double m = (double)S / cnt;
        double var = (double)Q / cnt - m * m;
        double s = (double)g1[t] / sqrt(var + 1e-5);
        double b = (double)b1[t];
        int k; bool fl;
        if (s > 0.0)      { double tt = fmin(fmax(m - b / s, -600.0), 600.0); k = (int)floor(tt);    fl = false; }
        else if (s < 0.0) { double tt = fmin(fmax(m - b / s, -600.0), 600.0); k = (int)ceil(tt) - 1; fl = true;  }
        else              { k = (b > 0.0) ? -601 : 601; fl = false; }
        thr1[t] = k;
        unsigned f = __ballot_sync(0xFFFFFFFFu, fl);
        if (t == 0) flip1 = f;
    }
    __syncthreads();

    // binarize h1 with pure integer compares, store to swizzled layout
    if (t < 196) {
        unsigned words[8] = {a.x, a.y, a.z, a.w, bb.x, bb.y, bb.z, bb.w};
        unsigned w = 0;
        #pragma unroll
        for (int k = 0; k < 8; k++) {
            unsigned wd = words[k];
            #pragma unroll
            for (int j = 0; j < 4; j++) {
                int c = k * 4 + j;
                int v = (int)(signed char)(wd >> (j * 8));
                w |= (unsigned)(v > thr1[c]) << c;
            }
        }
        int iy = t / 14, ix = t % 14;
        h1s[h1base(iy) + ix] = w ^ flip1;
    }
    __syncthreads();

    // thread = pair (y, x=2xp, 2xp+1) x 8 channels; warp owns co [wg*8, wg*8+8)
    int pr = t & 31, wg = t >> 5;
    int y = pr >> 2, xp = pr & 3;
    int co0 = wg * 8;

    // load 4x6 input window (rows 2y-2.., cols 4xp-2..) — conflict-free banks
    unsigned inw[24];
    #pragma unroll
    for (int r = 0; r < 4; r++) {
        int iy = 2 * y - 2 + r;
        bool rowOk = (iy >= 0) & (iy < 14);
        int rb = h1base(iy & 15);
        #pragma unroll
        for (int j = 0; j < 6; j++) {
            int ix = 4 * xp - 2 + j;
            bool valid = rowOk & (ix >= 0) & (ix < 14);
            inw[r * 6 + j] = valid ? h1s[rb + ix] : 0u;
        }
    }
    int cy  = (y == 0) ? 0 : ((y == 7) ? 2 : 1);
    int cx0 = (xp == 0) ? 0 : 1;
    int cx1 = (xp == 3) ? 2 : 1;
    int cls0 = cy * 3 + cx0, cls1 = cy * 3 + cx1;
    int nval0 = (cy == 1 ? 4 : 2) * (cx0 == 1 ? 4 : 2);
    int nval1 = (cy == 1 ? 4 : 2) * (cx1 == 1 ? 4 : 2);

    // border corrections: 8 shorts each via one 16B ldg (co0 is 8-aligned)
    int4 cc0 = __ldg((const int4*)(g_corr + cls0 * 64 + co0));
    int4 cc1 = __ldg((const int4*)(g_corr + cls1 * 64 + co0));
    const int* c0w = (const int*)&cc0;
    const int* c1w = (const int*)&cc1;

    const uint4* w2s4 = (const uint4*)w2s;
    unsigned u0[4], u1[4];
    int ssave = 0, qsave = 0;
    #pragma unroll
    for (int jj = 0; jj < 4; jj++) {            // pairs of channels
        int dpair0[2], dpair1[2];
        #pragma unroll
        for (int h = 0; h < 2; h++) {
            int j = 2 * jj + h;
            int co = co0 + j;
            int mm0 = 0, mm1 = 0;
            #pragma unroll
            for (int ky = 0; ky < 4; ky++) {    // one LDS.128 per row of taps
                uint4 w = w2s4[co * 4 + ky];
                mm0 += __popc(inw[ky * 6 + 0] ^ w.x) + __popc(inw[ky * 6 + 1] ^ w.y)
                     + __popc(inw[ky * 6 + 2] ^ w.z) + __popc(inw[ky * 6 + 3] ^ w.w);
                mm1 += __popc(inw[ky * 6 + 2] ^ w.x) + __popc(inw[ky * 6 + 3] ^ w.y)
                     + __popc(inw[ky * 6 + 4] ^ w.z) + __popc(inw[ky * 6 + 5] ^ w.w);
            }
            int cr0 = (int)(short)((c0w[j >> 1] >> ((j & 1) * 16)) & 0xFFFF);
            int cr1 = (int)(short)((c1w[j >> 1] >> ((j & 1) * 16)) & 0xFFFF);
            int d0 = 32 * nval0 - 2 * (mm0 - cr0);
            int d1 = 32 * nval1 - 2 * (mm1 - cr1);
            dpair0[h] = d0; dpair1[h] = d1;
            // fused stats2: warp-wide exact integer sums for channel co
            int s = __reduce_add_sync(0xFFFFFFFFu, d0 + d1);
            int q = __reduce_add_sync(0xFFFFFFFFu, d0 * d0 + d1 * d1);
            if (lane == j) { ssave = s; qsave = q; }
        }
        u0[jj] = ((unsigned)dpair0[0] & 0xFFFFu) | ((unsigned)dpair0[1] << 16);
        u1[jj] = ((unsigned)dpair1[0] & 0xFFFFu) | ((unsigned)dpair1[1] << 16);
    }
    // store both positions: [n][pos][co0..co0+7] int16 = one uint4 each
    int pos0 = y * 8 + 2 * xp;
    uint4* dst0 = (uint4*)(g_c2 + (size_t)n * 4096 + pos0 * 64 + co0);
    uint4* dst1 = (uint4*)(g_c2 + (size_t)n * 4096 + (pos0 + 1) * 64 + co0);
    dst0[0] = make_uint4(u0[0], u0[1], u0[2], u0[3]);
    dst1[0] = make_uint4(u1[0], u1[1], u1[2], u1[3]);

    // warp owns its 8 channels exclusively -> fire-and-forget REDs, lanes 0..7
    if (lane < 8) {
        atomicAdd(&g_stats[64 + co0 + lane],  (unsigned long long)(long long)ssave);
        atomicAdd(&g_stats[128 + co0 + lane], (unsigned long long)(long long)qsave);
    }
}

// ---------------- fc: 8 samples/block, full prefetch, vcmpgts2 binarize ------
__global__ void __launch_bounds__(256, 2) fc_kernel(const float* __restrict__ g2,
                                                    const float* __restrict__ b2) {
    __shared__ unsigned w3sA[640], w3sB[640];
    __shared__ short thk[64];
    __shared__ int flg[64];
    __shared__ unsigned thr2[32];
    __shared__ unsigned flipA, flipB;
    __shared__ int blkS[8][10], blkQ[8][10];

    int t = threadIdx.x, warp = t >> 5, lane = t & 31;
    #pragma unroll
    for (int i = 0; i < 3; i++) {
        int idx = t + i * 256;
        if (idx < 640) { w3sA[idx] = g_w3A[idx]; w3sB[idx] = g_w3B[idx]; }
    }
    if (t < 64) {
        long long S = (long long)g_stats[64 + t], Q = (long long)g_stats[128 + t];
        double cnt = 8192.0 * 64.0;
        double m = (double)S / cnt;
        double var = (double)Q / cnt - m * m;
        double s = (double)g2[t] / sqrt(var + 1e-5);
        double b = (double)b2[t];
        int k; int fl;
        if (s > 0.0)      { double tt = fmin(fmax(m - b / s, -600.0), 600.0); k = (int)floor(tt);    fl = 0; }
        else if (s < 0.0) { double tt = fmin(fmax(m - b / s, -600.0), 600.0); k = (int)ceil(tt) - 1; fl = 1; }
        else              { k = (b > 0.0) ? -601 : 601; fl = 0; }
        thk[t] = (short)k;
        flg[t] = fl;
    }
    __syncthreads();
    if (t < 32) thr2[t] = ((unsigned)(unsigned short)thk[2 * t]) | ((unsigned)(unsigned short)thk[2 * t + 1] << 16);
    if (t == 32) {
        unsigned fA = 0, fB = 0;
        #pragma unroll
        for (int j = 0; j < 16; j++) {
            fA |= ((unsigned)flg[2 * j] << j)      | ((unsigned)flg[2 * j + 1] << (16 + j));
            fB |= ((unsigned)flg[32 + 2 * j] << j) | ((unsigned)flg[33 + 2 * j] << (16 + j));
        }
        flipA = fA; flipB = fB;
    }
    __syncthreads();

    int samp = blockIdx.x * 8 + warp;

    // prefetch all 128 int16 (two positions) -> 16 outstanding LDG.128
    uint4 v[16];
    const uint4* src0 = (const uint4*)(g_c2 + (size_t)samp * 4096 + lane * 64);
    const uint4* src1 = (const uint4*)(g_c2 + (size_t)samp * 4096 + (lane + 32) * 64);
    #pragma unroll
    for (int k = 0; k < 8; k++) { v[k] = src0[k]; v[8 + k] = src1[k]; }

    int mm[10];
    #pragma unroll
    for (int o = 0; o < 10; o++) mm[o] = 0;

    #pragma unroll
    for (int pp = 0; pp < 2; pp++) {
        int p = lane + pp * 32;
        unsigned accA = 0, accB = 0;
        #pragma unroll
        for (int k = 0; k < 8; k++) {
            unsigned wv[4] = {v[pp * 8 + k].x, v[pp * 8 + k].y, v[pp * 8 + k].z, v[pp * 8 + k].w};
            #pragma unroll
            for (int i = 0; i < 4; i++) {
                int j = 4 * k + i;
                unsigned m = __vcmpgts2(wv[i], thr2[j]);   // SIMD int16 >, mask per half
                if (j < 16) accA |= (m << j)        & (0x00010001u << j);
                else        accB |= (m << (j - 16)) & (0x00010001u << (j - 16));
            }
        }
        accA ^= flipA; accB ^= flipB;
        #pragma unroll
        for (int o = 0; o < 10; o++)
            mm[o] += __popc(accA ^ w3sA[o * 64 + p]) + __popc(accB ^ w3sB[o * 64 + p]);
    }

    int r[10];
    #pragma unroll
    for (int o = 0; o < 10; o++)
        r[o] = 4096 - 2 * __reduce_add_sync(0xFFFFFFFFu, mm[o]);

    if (lane < 10) {
        int vv = 0;
        #pragma unroll
        for (int o = 0; o < 10; o++) if (lane == o) vv = r[o];
        g_fc[(size_t)samp * 10 + lane] = (short)vv;
        blkS[warp][lane] = vv;
        blkQ[warp][lane] = vv * vv;
    }
    __syncthreads();
    if (t < 10) {
        int s = 0, q = 0;
        #pragma unroll
        for (int w = 0; w < 8; w++) { s += blkS[w][t]; q += blkQ[w][t]; }
        atomicAdd(&g_stats[192 + t], (unsigned long long)(long long)s);
        atomicAdd(&g_stats[202 + t], (unsigned long long)(long long)q);
    }
}

// ---------------- final BN1d epilogue ----------------------------------------
__global__ void __launch_bounds__(256) out_kernel(const float* __restrict__ g3,
                                                  const float* __restrict__ b3,
                                                  float* __restrict__ out) {
    __shared__ float sc[10], sh[10];
    int t = threadIdx.x;
    if (t < 10) {
        long long s = (long long)g_stats[192 + t], q = (long long)g_stats[202 + t];
        double m   = (double)s / 8192.0;
        double var = (double)q / 8192.0 - m * m;
        double scale = (double)g3[t] / sqrt(var + 1e-5);
        sc[t] = (float)scale;
        sh[t] = (float)((double)b3[t] - m * scale);
    }
    __syncthreads();
    int i = blockIdx.x * 256 + t;
    if (i < BATCH * 10) {
        int o = i % 10;
        out[i] = fmaf((float)g_fc[i], sc[o], sh[o]);
    }
}

// ---------------- launch ------------------------------------------------------
extern "C" void kernel_launch(void* const* d_in, const int* in_sizes, int n_in,
                              void* d_out, int out_size) {
    const float* x  = (const float*)d_in[0];
    const float* w1 = (const float*)d_in[1];
    const float* g1 = (const float*)d_in[2];
    const float* b1 = (const float*)d_in[3];
    const float* w2 = (const float*)d_in[4];
    const float* g2 = (const float*)d_in[5];
    const float* b2 = (const float*)d_in[6];
    const float* w3 = (const float*)d_in[7];
    const float* g3 = (const float*)d_in[8];
    const float* b3 = (const float*)d_in[9];
    float* out = (float*)d_out;

    init_kernel<<<12, 256>>>(w1, w2, w3);
    conv1_kernel<<<BATCH, 224>>>(x);
    stats1_kernel<<<S1_BLOCKS, 256>>>();
    conv2_kernel<<<BATCH, 256>>>(g1, b1);   // 4th launch -> ncu capture slot
    fc_kernel<<<BATCH / 8, 256>>>(g2, b2);
    out_kernel<<<(BATCH * 10 + 255) / 256, 256>>>(g3, b3, out);
}